// round 7
// baseline (speedup 1.0000x reference)
#include <cuda_runtime.h>
#include <cuda_bf16.h>
#include <cstdint>
#include <math.h>

#define BB 4
#define SSZ 2048
#define DDIM 128
#define EPSV 1e-5f

// ---------------- scratch (static device globals; no allocations) ----------
__device__ float g_qnorm[BB * SSZ];
__device__ float g_knorm[BB * SSZ];
__device__ float g_partial[BB * SSZ * 16];
__device__ __nv_bfloat16 g_qhi[BB * SSZ * DDIM];
__device__ __nv_bfloat16 g_qlo[BB * SSZ * DDIM];
__device__ __nv_bfloat16 g_khi[BB * SSZ * DDIM];
__device__ __nv_bfloat16 g_klo[BB * SSZ * DDIM];
__device__ __nv_bfloat16 g_vthi[BB * DDIM * SSZ];   // V^T: [b][d][t]
__device__ __nv_bfloat16 g_vtlo[BB * DDIM * SSZ];
__device__ __nv_bfloat16 g_phi[(size_t)BB * SSZ * SSZ];  // unnormalized p hi
__device__ __nv_bfloat16 g_plo[(size_t)BB * SSZ * SSZ];  // unnormalized p lo

// ---------------- helpers ---------------------------------------------------
__device__ __forceinline__ uint32_t smem_u32(const void* p) {
    uint32_t a;
    asm("{ .reg .u64 t; cvta.to.shared.u64 t, %1; cvt.u32.u64 %0, t; }" : "=r"(a) : "l"(p));
    return a;
}
__device__ __forceinline__ void cpa16(uint32_t s, const void* g) {
    asm volatile("cp.async.cg.shared.global [%0], [%1], 16;" :: "r"(s), "l"(g));
}
#define CP_COMMIT() asm volatile("cp.async.commit_group;")
#define CP_WAIT(n)  asm volatile("cp.async.wait_group %0;" :: "n"(n))

__device__ __forceinline__ void ldm_x4(uint32_t r[4], uint32_t addr) {
    asm volatile("ldmatrix.sync.aligned.m8n8.x4.shared.b16 {%0,%1,%2,%3}, [%4];"
        : "=r"(r[0]), "=r"(r[1]), "=r"(r[2]), "=r"(r[3]) : "r"(addr));
}
__device__ __forceinline__ void mma16816(float c[4], const uint32_t a[4],
                                         uint32_t b0, uint32_t b1) {
    asm volatile("mma.sync.aligned.m16n8k16.row.col.f32.bf16.bf16.f32 "
        "{%0,%1,%2,%3}, {%4,%5,%6,%7}, {%8,%9}, {%0,%1,%2,%3};"
        : "+f"(c[0]), "+f"(c[1]), "+f"(c[2]), "+f"(c[3])
        : "r"(a[0]), "r"(a[1]), "r"(a[2]), "r"(a[3]), "r"(b0), "r"(b1));
}
__device__ __forceinline__ void split2(float a, float b,
                                       __nv_bfloat162& h, __nv_bfloat162& l) {
    h = __floats2bfloat162_rn(a, b);
    l = __floats2bfloat162_rn(a - __bfloat162float(h.x), b - __bfloat162float(h.y));
}

// ---------------- Kernel 1: row norms + Q/K bf16 hi/lo split ----------------
__global__ __launch_bounds__(256) void hyp_norms(const float* __restrict__ q,
                                                 const float* __restrict__ k) {
    int warp = (blockIdx.x * blockDim.x + threadIdx.x) >> 5;
    int lane = threadIdx.x & 31;
    const int R = BB * SSZ;
    if (warp >= 2 * R) return;
    const bool isq = warp < R;
    const int row = isq ? warp : warp - R;
    const float* src = (isq ? q : k) + (size_t)row * DDIM;
    float4 v = ((const float4*)src)[lane];
    float s = v.x * v.x + v.y * v.y + v.z * v.z + v.w * v.w;
#pragma unroll
    for (int o = 16; o; o >>= 1) s += __shfl_xor_sync(0xffffffffu, s, o);
    if (lane == 0) { if (isq) g_qnorm[row] = s; else g_knorm[row] = s; }
    __nv_bfloat162 h0, l0, h1, l1;
    split2(v.x, v.y, h0, l0);
    split2(v.z, v.w, h1, l1);
    __nv_bfloat16* hi = (isq ? g_qhi : g_khi) + (size_t)row * DDIM + lane * 4;
    __nv_bfloat16* lo = (isq ? g_qlo : g_klo) + (size_t)row * DDIM + lane * 4;
    *(__nv_bfloat162*)(hi)     = h0;
    *(__nv_bfloat162*)(hi + 2) = h1;
    *(__nv_bfloat162*)(lo)     = l0;
    *(__nv_bfloat162*)(lo + 2) = l1;
}

// ---------------- Kernel 2: V^T + bf16 hi/lo split ---------------------------
__global__ void hyp_vt(const float* __restrict__ v) {
    __shared__ float tile[32][33];
    const int b = blockIdx.z, t0 = blockIdx.x * 32, d0 = blockIdx.y * 32;
    const int tx = threadIdx.x, ty = threadIdx.y;
#pragma unroll
    for (int i = 0; i < 4; i++)
        tile[ty + 8 * i][tx] = v[((size_t)(b * SSZ) + t0 + ty + 8 * i) * DDIM + d0 + tx];
    __syncthreads();
#pragma unroll
    for (int i = 0; i < 4; i++) {
        float x = tile[tx][ty + 8 * i];
        __nv_bfloat16 hi = __float2bfloat16_rn(x);
        __nv_bfloat16 lo = __float2bfloat16_rn(x - __bfloat162float(hi));
        size_t idx = ((size_t)(b * DDIM) + d0 + ty + 8 * i) * SSZ + t0 + tx;
        g_vthi[idx] = hi; g_vtlo[idx] = lo;
    }
}

// ---------------- Kernel 3: QK^T (HMMA hi/lo x3) + hyperbolic numerator -----
// 128x128 tile/CTA, 8 warps 2x4, warp tile 64x32. Writes ONLY bf16 hi/lo p.
// smem: qn@0 kn@512 iq@1024 ik@1536 rp@2048 | tiles@4096: qhi,qlo,khi,klo
#define QPAD 136
#define QK_TB (128 * QPAD * 2)             // bytes per operand tile
#define QK_SMEM (4096 + 4 * QK_TB)
__global__ void __launch_bounds__(256, 1)
hyp_qk(const float* __restrict__ cp, const float* __restrict__ betap) {
    extern __shared__ __align__(16) char smem[];
    float* qn_s = (float*)smem;
    float* kn_s = (float*)(smem + 512);
    float* iq_s = (float*)(smem + 1024);
    float* ik_s = (float*)(smem + 1536);
    float* rp_s = (float*)(smem + 2048);
    const uint32_t sb = smem_u32(smem);
    const uint32_t t_qh = sb + 4096, t_ql = t_qh + QK_TB;
    const uint32_t t_kh = t_ql + QK_TB, t_kl = t_kh + QK_TB;

    const int tid = threadIdx.x, wid = tid >> 5, lane = tid & 31;
    const int bxx = blockIdx.x, b = blockIdx.z;
    const int row0 = blockIdx.y * 128, col0 = bxx * 128;
    const float c = *cp;

    if (tid < 128) {
        float qn = g_qnorm[b * SSZ + row0 + tid];
        float kn = g_knorm[b * SSZ + col0 + tid];
        qn_s[tid] = qn; kn_s[tid] = kn;
        iq_s[tid] = 1.f / fmaxf(1.f - c * qn, 1e-12f);
        ik_s[tid] = 1.f / fmaxf(1.f - c * kn, 1e-12f);
    }

    {
        const __nv_bfloat16* gq_h = g_qhi + (size_t)(b * SSZ + row0) * DDIM;
        const __nv_bfloat16* gq_l = g_qlo + (size_t)(b * SSZ + row0) * DDIM;
        const __nv_bfloat16* gk_h = g_khi + (size_t)(b * SSZ + col0) * DDIM;
        const __nv_bfloat16* gk_l = g_klo + (size_t)(b * SSZ + col0) * DDIM;
#pragma unroll
        for (int it = 0; it < 8; it++) {
            int i = tid + 256 * it;
            int r = i >> 4, g = i & 15;
            uint32_t so = (uint32_t)(r * (QPAD * 2) + g * 16);
            size_t go = (size_t)r * DDIM + g * 8;
            cpa16(t_qh + so, gq_h + go);
            cpa16(t_ql + so, gq_l + go);
            cpa16(t_kh + so, gk_h + go);
            cpa16(t_kl + so, gk_l + go);
        }
    }
    CP_COMMIT();
    CP_WAIT(0);
    __syncthreads();

    const int wr = wid >> 2, wc = wid & 3;
    const int m0 = wr * 64, n0 = wc * 32;
    const int alr = lane & 15, alc = (lane >> 4) * 8;

    float acc[4][4][4];
#pragma unroll
    for (int i = 0; i < 4; i++)
#pragma unroll
        for (int j = 0; j < 4; j++)
#pragma unroll
            for (int r = 0; r < 4; r++) acc[i][j][r] = 0.f;

#pragma unroll
    for (int ks = 0; ks < 8; ks++) {
        uint32_t ah[4][4], al[4][4], bh[2][4], bl[2][4];
        const int kel = ks * 16 + alc;
#pragma unroll
        for (int fm = 0; fm < 4; fm++) {
            uint32_t off = (uint32_t)(((m0 + fm * 16 + alr) * QPAD + kel) * 2);
            ldm_x4(ah[fm], t_qh + off);
            ldm_x4(al[fm], t_ql + off);
        }
#pragma unroll
        for (int h = 0; h < 2; h++) {
            uint32_t off = (uint32_t)(((n0 + h * 16 + alr) * QPAD + kel) * 2);
            ldm_x4(bh[h], t_kh + off);
            ldm_x4(bl[h], t_kl + off);
        }
#pragma unroll
        for (int fm = 0; fm < 4; fm++)
#pragma unroll
            for (int fn = 0; fn < 4; fn++) {
                int h = fn >> 1, s = fn & 1;
                mma16816(acc[fm][fn], ah[fm], bh[h][s], bh[h][s + 2]);
                mma16816(acc[fm][fn], ah[fm], bl[h][s], bl[h][s + 2]);
                mma16816(acc[fm][fn], al[fm], bh[h][s], bh[h][s + 2]);
            }
    }

    // epilogue: p = u^(-bp/sqrt(c)), u = (1+x)+sqrt(x(x+2)); bias cancels
    const float sqrtc = sqrtf(c);
    const float beta = *betap;
    const float bp = fmaxf(beta, 0.f) + log1pf(expf(-fabsf(beta)));  // softplus
    const float e2 = bp / sqrtc;
    const float tcc = 2.f * c;

    __nv_bfloat16* ph = g_phi + ((size_t)(b * SSZ + row0)) * SSZ + col0;
    __nv_bfloat16* pl = g_plo + ((size_t)(b * SSZ + row0)) * SSZ + col0;
#pragma unroll
    for (int fm = 0; fm < 4; fm++) {
        const int r1 = m0 + fm * 16 + (lane >> 2), r2 = r1 + 8;
        const float qn1 = qn_s[r1], qn2 = qn_s[r2];
        const float iq1 = iq_s[r1], iq2 = iq_s[r2];
        float s1 = 0.f, s2 = 0.f;
#pragma unroll
        for (int fn = 0; fn < 4; fn++) {
            const int cc = n0 + fn * 8 + (lane & 3) * 2;
            const float kn0 = kn_s[cc], kn1 = kn_s[cc + 1];
            const float ik0 = ik_s[cc], ik1 = ik_s[cc + 1];
            float pv[4];
#pragma unroll
            for (int rr = 0; rr < 2; rr++) {
                float qn = rr ? qn2 : qn1, iq = rr ? iq2 : iq1;
#pragma unroll
                for (int jj = 0; jj < 2; jj++) {
                    float dot = acc[fm][fn][rr * 2 + jj];
                    float kn = jj ? kn1 : kn0, ik = jj ? ik1 : ik0;
                    float x = tcc * (qn + kn - 2.f * dot) * iq * ik;
                    x = fmaxf(x, EPSV);
                    float t = x * (x + 2.f);
                    float u = (1.f + x) + t * rsqrtf(t);
                    float p = exp2f(-e2 * __log2f(u));
                    pv[rr * 2 + jj] = p;
                    if (rr) s2 += p; else s1 += p;
                }
            }
            __nv_bfloat162 h, l;
            split2(pv[0], pv[1], h, l);
            *(__nv_bfloat162*)(ph + (size_t)r1 * SSZ + cc) = h;
            *(__nv_bfloat162*)(pl + (size_t)r1 * SSZ + cc) = l;
            split2(pv[2], pv[3], h, l);
            *(__nv_bfloat162*)(ph + (size_t)r2 * SSZ + cc) = h;
            *(__nv_bfloat162*)(pl + (size_t)r2 * SSZ + cc) = l;
        }
        s1 += __shfl_xor_sync(0xffffffffu, s1, 1);
        s1 += __shfl_xor_sync(0xffffffffu, s1, 2);
        s2 += __shfl_xor_sync(0xffffffffu, s2, 1);
        s2 += __shfl_xor_sync(0xffffffffu, s2, 2);
        if ((lane & 3) == 0) {
            rp_s[r1 * 4 + wc] = s1;
            rp_s[r2 * 4 + wc] = s2;
        }
    }
    __syncthreads();
    if (tid < 128) {
        float s = rp_s[tid * 4] + rp_s[tid * 4 + 1] + rp_s[tid * 4 + 2] + rp_s[tid * 4 + 3];
        g_partial[((size_t)(b * SSZ + row0 + tid)) * 16 + bxx] = s;
    }
}

// ---------------- Kernel 4: O = expmap0((P V)/rowsum), W = P/rowsum ---------
// 64(M) x 128(N=D) per CTA, 8 warps 2x4. K=2048 in 64-chunks, cp.async 2-stage.
// Also emits the normalized fp32 weights tile from each resident p chunk.
// smem: inv@0(256B) rp@512(1KB) | buffers@2048: {whi,wlo[64][72], vhi,vlo[128][72]} x2
#define APAD 72
#define AV_WT (64 * APAD)
#define AV_VT (128 * APAD)
#define AV_BUF (2 * AV_WT + 2 * AV_VT)
#define AV_SMEM (2048 + 2 * AV_BUF * 2)
__global__ void __launch_bounds__(256, 1)
hyp_av(const float* __restrict__ cp, float* __restrict__ W,
       float* __restrict__ out) {
    extern __shared__ __align__(16) char smem[];
    float* inv_s = (float*)smem;
    float* rp_s = (float*)(smem + 512);
    const uint32_t sb = smem_u32(smem);

    const int tid = threadIdx.x, wid = tid >> 5, lane = tid & 31;
    const int b = blockIdx.z;
    const int row0 = blockIdx.x * 64;

    if (tid < 64) {
        float s = 0.f;
#pragma unroll
        for (int i = 0; i < 16; i++)
            s += g_partial[((size_t)(b * SSZ + row0 + tid)) * 16 + i];
        inv_s[tid] = 1.f / s;
    }

    const __nv_bfloat16* pb_h = g_phi + ((size_t)(b * SSZ + row0)) * SSZ;
    const __nv_bfloat16* pb_l = g_plo + ((size_t)(b * SSZ + row0)) * SSZ;
    const __nv_bfloat16* vth = g_vthi + (size_t)b * DDIM * SSZ;
    const __nv_bfloat16* vtl = g_vtlo + (size_t)b * DDIM * SSZ;
    float* wrow = W + ((size_t)(b * SSZ + row0)) * SSZ;

    const uint32_t buf0 = sb + 2048;
    const uint32_t o_wl = AV_WT * 2, o_vh = 2 * AV_WT * 2, o_vl = o_vh + AV_VT * 2;

    auto load_chunk = [&](int stage, int t0) {
        uint32_t base = buf0 + stage * (AV_BUF * 2);
#pragma unroll
        for (int it = 0; it < 2; it++) {
            int i = tid + 256 * it;
            int r = i >> 3, g = i & 7;
            uint32_t so = (uint32_t)(r * (APAD * 2) + g * 16);
            size_t go = (size_t)r * SSZ + t0 + g * 8;
            cpa16(base + so, pb_h + go);
            cpa16(base + o_wl + so, pb_l + go);
        }
#pragma unroll
        for (int it = 0; it < 4; it++) {
            int i = tid + 256 * it;
            int d = i >> 3, g = i & 7;
            uint32_t so = (uint32_t)(d * (APAD * 2) + g * 16);
            size_t go = (size_t)d * SSZ + t0 + g * 8;
            cpa16(base + o_vh + so, vth + go);
            cpa16(base + o_vl + so, vtl + go);
        }
    };

    const int wr = wid >> 2, wc = wid & 3;
    const int m0 = wr * 32, n0 = wc * 32;
    const int alr = lane & 15, alc = (lane >> 4) * 8;

    float acc[2][4][4];
#pragma unroll
    for (int i = 0; i < 2; i++)
#pragma unroll
        for (int j = 0; j < 4; j++)
#pragma unroll
            for (int r = 0; r < 4; r++) acc[i][j][r] = 0.f;

    load_chunk(0, 0);
    CP_COMMIT();

    for (int kc = 0; kc < 32; kc++) {
        if (kc < 31) {
            load_chunk((kc + 1) & 1, (kc + 1) * 64);
            CP_COMMIT();
            CP_WAIT(1);
        } else {
            CP_WAIT(0);
        }
        __syncthreads();

        uint32_t base = buf0 + (kc & 1) * (AV_BUF * 2);
        const __nv_bfloat16* sh = (const __nv_bfloat16*)(smem + 2048
                                   + (kc & 1) * (AV_BUF * 2));
        const __nv_bfloat16* sl = sh + AV_WT;

        // emit normalized fp32 W tile from resident p chunk (coalesced)
        {
            const int t0 = kc * 64;
#pragma unroll
            for (int it = 0; it < 4; it++) {
                int i = tid + 256 * it;
                int r = i >> 4, cg = (i & 15) * 4;
                float inv = inv_s[r];
                __nv_bfloat162 h0 = *(const __nv_bfloat162*)(sh + r * APAD + cg);
                __nv_bfloat162 h1 = *(const __nv_bfloat162*)(sh + r * APAD + cg + 2);
                __nv_bfloat162 l0 = *(const __nv_bfloat162*)(sl + r * APAD + cg);
                __nv_bfloat162 l1 = *(const __nv_bfloat162*)(sl + r * APAD + cg + 2);
                float4 w;
                w.x = (__bfloat162float(h0.x) + __bfloat162float(l0.x)) * inv;
                w.y = (__bfloat162float(h0.y) + __bfloat162float(l0.y)) * inv;
                w.z = (__bfloat162float(h1.x) + __bfloat162float(l1.x)) * inv;
                w.w = (__bfloat162float(h1.y) + __bfloat162float(l1.y)) * inv;
                *(float4*)(wrow + (size_t)r * SSZ + t0 + cg) = w;
            }
        }

#pragma unroll
        for (int ks = 0; ks < 4; ks++) {
            uint32_t ah[2][4], al[2][4], bh[2][4], bl[2][4];
            const int kel = ks * 16 + alc;
#pragma unroll
            for (int fm = 0; fm < 2; fm++) {
                uint32_t off = (uint32_t)(((m0 + fm * 16 + alr) * APAD + kel) * 2);
                ldm_x4(ah[fm], base + off);
                ldm_x4(al[fm], base + o_wl + off);
            }
#pragma unroll
            for (int h = 0; h < 2; h++) {
                uint32_t off = (uint32_t)(((n0 + h * 16 + alr) * APAD + kel) * 2);
                ldm_x4(bh[h], base + o_vh + off);
                ldm_x4(bl[h], base + o_vl + off);
            }
#pragma unroll
            for (int fm = 0; fm < 2; fm++)
#pragma unroll
                for (int fn = 0; fn < 4; fn++) {
                    int h = fn >> 1, s = fn & 1;
                    mma16816(acc[fm][fn], ah[fm], bh[h][s], bh[h][s + 2]);
                    mma16816(acc[fm][fn], ah[fm], bl[h][s], bl[h][s + 2]);
                    mma16816(acc[fm][fn], al[fm], bh[h][s], bh[h][s + 2]);
                }
        }
        __syncthreads();
    }

    // epilogue: normalize by rowsum, then exp-map at origin
#pragma unroll
    for (int fm = 0; fm < 2; fm++) {
        const int r1 = m0 + fm * 16 + (lane >> 2), r2 = r1 + 8;
        const float i1 = inv_s[r1], i2 = inv_s[r2];
        float s1 = 0.f, s2 = 0.f;
#pragma unroll
        for (int fn = 0; fn < 4; fn++) {
            acc[fm][fn][0] *= i1; acc[fm][fn][1] *= i1;
            acc[fm][fn][2] *= i2; acc[fm][fn][3] *= i2;
            s1 += acc[fm][fn][0] * acc[fm][fn][0] + acc[fm][fn][1] * acc[fm][fn][1];
            s2 += acc[fm][fn][2] * acc[fm][fn][2] + acc[fm][fn][3] * acc[fm][fn][3];
        }
        s1 += __shfl_xor_sync(0xffffffffu, s1, 1);
        s1 += __shfl_xor_sync(0xffffffffu, s1, 2);
        s2 += __shfl_xor_sync(0xffffffffu, s2, 1);
        s2 += __shfl_xor_sync(0xffffffffu, s2, 2);
        if ((lane & 3) == 0) {
            rp_s[r1 * 4 + wc] = s1;
            rp_s[r2 * 4 + wc] = s2;
        }
    }
    __syncthreads();
    const float c = *cp, sqrtc = sqrtf(c);
    float* sc_s = inv_s;   // reuse after inv consumed
    if (tid < 64) {
        float ns = rp_s[tid * 4] + rp_s[tid * 4 + 1] + rp_s[tid * 4 + 2] + rp_s[tid * 4 + 3];
        float vn = fmaxf(sqrtf(ns), EPSV);
        sc_s[tid] = tanhf(sqrtc * vn) / (sqrtc * vn);
    }
    __syncthreads();

    float* ob = out + ((size_t)(b * SSZ + row0)) * DDIM;
#pragma unroll
    for (int fm = 0; fm < 2; fm++) {
        const int r1 = m0 + fm * 16 + (lane >> 2), r2 = r1 + 8;
        const float sc1 = sc_s[r1], sc2 = sc_s[r2];
#pragma unroll
        for (int fn = 0; fn < 4; fn++) {
            const int cc = n0 + fn * 8 + (lane & 3) * 2;
            *(float2*)(ob + (size_t)r1 * DDIM + cc) =
                make_float2(acc[fm][fn][0] * sc1, acc[fm][fn][1] * sc1);
            *(float2*)(ob + (size_t)r2 * DDIM + cc) =
                make_float2(acc[fm][fn][2] * sc2, acc[fm][fn][3] * sc2);
        }
    }
}

// ---------------------------------------------------------------------------
extern "C" void kernel_launch(void* const* d_in, const int* in_sizes, int n_in,
                              void* d_out, int out_size) {
    const float* q    = (const float*)d_in[0];
    const float* k    = (const float*)d_in[1];
    const float* v    = (const float*)d_in[2];
    const float* c    = (const float*)d_in[3];
    const float* beta = (const float*)d_in[4];

    float* out = (float*)d_out;                   // output_hyperbolic (B,S,D)
    float* W   = out + (size_t)BB * SSZ * DDIM;   // attention_weights (B,S,S)

    cudaFuncSetAttribute(hyp_qk, cudaFuncAttributeMaxDynamicSharedMemorySize, QK_SMEM);
    cudaFuncSetAttribute(hyp_av, cudaFuncAttributeMaxDynamicSharedMemorySize, AV_SMEM);

    hyp_norms<<<2 * BB * SSZ / 8, 256>>>(q, k);
    hyp_vt<<<dim3(SSZ / 32, DDIM / 32, BB), dim3(32, 8)>>>(v);
    hyp_qk<<<dim3(SSZ / 128, SSZ / 128, BB), 256, QK_SMEM>>>(c, beta);
    hyp_av<<<dim3(SSZ / 64, 1, BB), 256, AV_SMEM>>>(c, W, out);
}

// round 8
// speedup vs baseline: 1.3042x; 1.3042x over previous
#include <cuda_runtime.h>
#include <cuda_bf16.h>
#include <cstdint>
#include <math.h>

#define BB 4
#define SSZ 2048
#define DDIM 128
#define EPSV 1e-5f

// ---------------- scratch (static device globals; no allocations) ----------
__device__ float g_qnorm[BB * SSZ];
__device__ float g_knorm[BB * SSZ];
__device__ float g_partial[BB * SSZ * 16];
__device__ __nv_bfloat16 g_qhi[BB * SSZ * DDIM];
__device__ __nv_bfloat16 g_qlo[BB * SSZ * DDIM];
__device__ __nv_bfloat16 g_khi[BB * SSZ * DDIM];
__device__ __nv_bfloat16 g_klo[BB * SSZ * DDIM];
__device__ __nv_bfloat16 g_vthi[BB * DDIM * SSZ];   // V^T: [b][d][t]
__device__ __nv_bfloat16 g_vtlo[BB * DDIM * SSZ];
__device__ __nv_bfloat16 g_phi[(size_t)BB * SSZ * SSZ];  // unnormalized p hi
__device__ __nv_bfloat16 g_plo[(size_t)BB * SSZ * SSZ];  // unnormalized p lo

// ---------------- helpers ---------------------------------------------------
__device__ __forceinline__ uint32_t smem_u32(const void* p) {
    uint32_t a;
    asm("{ .reg .u64 t; cvta.to.shared.u64 t, %1; cvt.u32.u64 %0, t; }" : "=r"(a) : "l"(p));
    return a;
}
__device__ __forceinline__ void cpa16(uint32_t s, const void* g) {
    asm volatile("cp.async.cg.shared.global [%0], [%1], 16;" :: "r"(s), "l"(g));
}
#define CP_COMMIT() asm volatile("cp.async.commit_group;")
#define CP_WAIT(n)  asm volatile("cp.async.wait_group %0;" :: "n"(n))

__device__ __forceinline__ void ldm_x4(uint32_t r[4], uint32_t addr) {
    asm volatile("ldmatrix.sync.aligned.m8n8.x4.shared.b16 {%0,%1,%2,%3}, [%4];"
        : "=r"(r[0]), "=r"(r[1]), "=r"(r[2]), "=r"(r[3]) : "r"(addr));
}
__device__ __forceinline__ void mma16816(float c[4], const uint32_t a[4],
                                         uint32_t b0, uint32_t b1) {
    asm volatile("mma.sync.aligned.m16n8k16.row.col.f32.bf16.bf16.f32 "
        "{%0,%1,%2,%3}, {%4,%5,%6,%7}, {%8,%9}, {%0,%1,%2,%3};"
        : "+f"(c[0]), "+f"(c[1]), "+f"(c[2]), "+f"(c[3])
        : "r"(a[0]), "r"(a[1]), "r"(a[2]), "r"(a[3]), "r"(b0), "r"(b1));
}
__device__ __forceinline__ void split2(float a, float b,
                                       __nv_bfloat162& h, __nv_bfloat162& l) {
    h = __floats2bfloat162_rn(a, b);
    l = __floats2bfloat162_rn(a - __bfloat162float(h.x), b - __bfloat162float(h.y));
}

// ---------------- Kernel 1: row norms + Q/K bf16 hi/lo split ----------------
__global__ __launch_bounds__(256) void hyp_norms(const float* __restrict__ q,
                                                 const float* __restrict__ k) {
    int warp = (blockIdx.x * blockDim.x + threadIdx.x) >> 5;
    int lane = threadIdx.x & 31;
    const int R = BB * SSZ;
    if (warp >= 2 * R) return;
    const bool isq = warp < R;
    const int row = isq ? warp : warp - R;
    const float* src = (isq ? q : k) + (size_t)row * DDIM;
    float4 v = ((const float4*)src)[lane];
    float s = v.x * v.x + v.y * v.y + v.z * v.z + v.w * v.w;
#pragma unroll
    for (int o = 16; o; o >>= 1) s += __shfl_xor_sync(0xffffffffu, s, o);
    if (lane == 0) { if (isq) g_qnorm[row] = s; else g_knorm[row] = s; }
    __nv_bfloat162 h0, l0, h1, l1;
    split2(v.x, v.y, h0, l0);
    split2(v.z, v.w, h1, l1);
    __nv_bfloat16* hi = (isq ? g_qhi : g_khi) + (size_t)row * DDIM + lane * 4;
    __nv_bfloat16* lo = (isq ? g_qlo : g_klo) + (size_t)row * DDIM + lane * 4;
    *(__nv_bfloat162*)(hi)     = h0;
    *(__nv_bfloat162*)(hi + 2) = h1;
    *(__nv_bfloat162*)(lo)     = l0;
    *(__nv_bfloat162*)(lo + 2) = l1;
}

// ---------------- Kernel 2: V^T + bf16 hi/lo split ---------------------------
__global__ void hyp_vt(const float* __restrict__ v) {
    __shared__ float tile[32][33];
    const int b = blockIdx.z, t0 = blockIdx.x * 32, d0 = blockIdx.y * 32;
    const int tx = threadIdx.x, ty = threadIdx.y;
#pragma unroll
    for (int i = 0; i < 4; i++)
        tile[ty + 8 * i][tx] = v[((size_t)(b * SSZ) + t0 + ty + 8 * i) * DDIM + d0 + tx];
    __syncthreads();
#pragma unroll
    for (int i = 0; i < 4; i++) {
        float x = tile[tx][ty + 8 * i];
        __nv_bfloat16 hi = __float2bfloat16_rn(x);
        __nv_bfloat16 lo = __float2bfloat16_rn(x - __bfloat162float(hi));
        size_t idx = ((size_t)(b * DDIM) + d0 + ty + 8 * i) * SSZ + t0 + tx;
        g_vthi[idx] = hi; g_vtlo[idx] = lo;
    }
}

// ---------------- Kernel 3: QK^T (HMMA hi/lo x3) + hyperbolic numerator -----
// 128x128 tile/CTA, 8 warps 2x4, warp tile 64x32. Writes ONLY bf16 hi/lo p.
#define QPAD 136
#define QK_TB (128 * QPAD * 2)
#define QK_SMEM (4096 + 4 * QK_TB)
__global__ void __launch_bounds__(256, 1)
hyp_qk(const float* __restrict__ cp, const float* __restrict__ betap) {
    extern __shared__ __align__(16) char smem[];
    float* qn_s = (float*)smem;
    float* kn_s = (float*)(smem + 512);
    float* iq_s = (float*)(smem + 1024);
    float* ik_s = (float*)(smem + 1536);
    float* rp_s = (float*)(smem + 2048);
    const uint32_t sb = smem_u32(smem);
    const uint32_t t_qh = sb + 4096, t_ql = t_qh + QK_TB;
    const uint32_t t_kh = t_ql + QK_TB, t_kl = t_kh + QK_TB;

    const int tid = threadIdx.x, wid = tid >> 5, lane = tid & 31;
    const int bxx = blockIdx.x, b = blockIdx.z;
    const int row0 = blockIdx.y * 128, col0 = bxx * 128;
    const float c = *cp;

    if (tid < 128) {
        float qn = g_qnorm[b * SSZ + row0 + tid];
        float kn = g_knorm[b * SSZ + col0 + tid];
        qn_s[tid] = qn; kn_s[tid] = kn;
        iq_s[tid] = 1.f / fmaxf(1.f - c * qn, 1e-12f);
        ik_s[tid] = 1.f / fmaxf(1.f - c * kn, 1e-12f);
    }

    {
        const __nv_bfloat16* gq_h = g_qhi + (size_t)(b * SSZ + row0) * DDIM;
        const __nv_bfloat16* gq_l = g_qlo + (size_t)(b * SSZ + row0) * DDIM;
        const __nv_bfloat16* gk_h = g_khi + (size_t)(b * SSZ + col0) * DDIM;
        const __nv_bfloat16* gk_l = g_klo + (size_t)(b * SSZ + col0) * DDIM;
#pragma unroll
        for (int it = 0; it < 8; it++) {
            int i = tid + 256 * it;
            int r = i >> 4, g = i & 15;
            uint32_t so = (uint32_t)(r * (QPAD * 2) + g * 16);
            size_t go = (size_t)r * DDIM + g * 8;
            cpa16(t_qh + so, gq_h + go);
            cpa16(t_ql + so, gq_l + go);
            cpa16(t_kh + so, gk_h + go);
            cpa16(t_kl + so, gk_l + go);
        }
    }
    CP_COMMIT();
    CP_WAIT(0);
    __syncthreads();

    const int wr = wid >> 2, wc = wid & 3;
    const int m0 = wr * 64, n0 = wc * 32;
    const int alr = lane & 15, alc = (lane >> 4) * 8;

    float acc[4][4][4];
#pragma unroll
    for (int i = 0; i < 4; i++)
#pragma unroll
        for (int j = 0; j < 4; j++)
#pragma unroll
            for (int r = 0; r < 4; r++) acc[i][j][r] = 0.f;

#pragma unroll
    for (int ks = 0; ks < 8; ks++) {
        uint32_t ah[4][4], al[4][4], bh[2][4], bl[2][4];
        const int kel = ks * 16 + alc;
#pragma unroll
        for (int fm = 0; fm < 4; fm++) {
            uint32_t off = (uint32_t)(((m0 + fm * 16 + alr) * QPAD + kel) * 2);
            ldm_x4(ah[fm], t_qh + off);
            ldm_x4(al[fm], t_ql + off);
        }
#pragma unroll
        for (int h = 0; h < 2; h++) {
            uint32_t off = (uint32_t)(((n0 + h * 16 + alr) * QPAD + kel) * 2);
            ldm_x4(bh[h], t_kh + off);
            ldm_x4(bl[h], t_kl + off);
        }
#pragma unroll
        for (int fm = 0; fm < 4; fm++)
#pragma unroll
            for (int fn = 0; fn < 4; fn++) {
                int h = fn >> 1, s = fn & 1;
                mma16816(acc[fm][fn], ah[fm], bh[h][s], bh[h][s + 2]);
                mma16816(acc[fm][fn], ah[fm], bl[h][s], bl[h][s + 2]);
                mma16816(acc[fm][fn], al[fm], bh[h][s], bh[h][s + 2]);
            }
    }

    const float sqrtc = sqrtf(c);
    const float beta = *betap;
    const float bp = fmaxf(beta, 0.f) + log1pf(expf(-fabsf(beta)));  // softplus
    const float e2 = bp / sqrtc;
    const float tcc = 2.f * c;

    __nv_bfloat16* ph = g_phi + ((size_t)(b * SSZ + row0)) * SSZ + col0;
    __nv_bfloat16* pl = g_plo + ((size_t)(b * SSZ + row0)) * SSZ + col0;
#pragma unroll
    for (int fm = 0; fm < 4; fm++) {
        const int r1 = m0 + fm * 16 + (lane >> 2), r2 = r1 + 8;
        const float qn1 = qn_s[r1], qn2 = qn_s[r2];
        const float iq1 = iq_s[r1], iq2 = iq_s[r2];
        float s1 = 0.f, s2 = 0.f;
#pragma unroll
        for (int fn = 0; fn < 4; fn++) {
            const int cc = n0 + fn * 8 + (lane & 3) * 2;
            const float kn0 = kn_s[cc], kn1 = kn_s[cc + 1];
            const float ik0 = ik_s[cc], ik1 = ik_s[cc + 1];
            float pv[4];
#pragma unroll
            for (int rr = 0; rr < 2; rr++) {
                float qn = rr ? qn2 : qn1, iq = rr ? iq2 : iq1;
#pragma unroll
                for (int jj = 0; jj < 2; jj++) {
                    float dot = acc[fm][fn][rr * 2 + jj];
                    float kn = jj ? kn1 : kn0, ik = jj ? ik1 : ik0;
                    float x = tcc * (qn + kn - 2.f * dot) * iq * ik;
                    x = fmaxf(x, EPSV);
                    float t = x * (x + 2.f);
                    float u = (1.f + x) + t * rsqrtf(t);
                    float p = exp2f(-e2 * __log2f(u));
                    pv[rr * 2 + jj] = p;
                    if (rr) s2 += p; else s1 += p;
                }
            }
            __nv_bfloat162 h, l;
            split2(pv[0], pv[1], h, l);
            *(__nv_bfloat162*)(ph + (size_t)r1 * SSZ + cc) = h;
            *(__nv_bfloat162*)(pl + (size_t)r1 * SSZ + cc) = l;
            split2(pv[2], pv[3], h, l);
            *(__nv_bfloat162*)(ph + (size_t)r2 * SSZ + cc) = h;
            *(__nv_bfloat162*)(pl + (size_t)r2 * SSZ + cc) = l;
        }
        s1 += __shfl_xor_sync(0xffffffffu, s1, 1);
        s1 += __shfl_xor_sync(0xffffffffu, s1, 2);
        s2 += __shfl_xor_sync(0xffffffffu, s2, 1);
        s2 += __shfl_xor_sync(0xffffffffu, s2, 2);
        if ((lane & 3) == 0) {
            rp_s[r1 * 4 + wc] = s1;
            rp_s[r2 * 4 + wc] = s2;
        }
    }
    __syncthreads();
    if (tid < 128) {
        float s = rp_s[tid * 4] + rp_s[tid * 4 + 1] + rp_s[tid * 4 + 2] + rp_s[tid * 4 + 3];
        g_partial[((size_t)(b * SSZ + row0 + tid)) * 16 + bxx] = s;
    }
}

// ---------------- Kernel 4: W = (p_hi + p_lo) / rowsum  (streaming) ---------
__global__ __launch_bounds__(256) void hyp_norm_w(float* __restrict__ W) {
    const int row = blockIdx.x;
    float s = 0.f;
#pragma unroll
    for (int i = 0; i < 16; i++) s += g_partial[(size_t)row * 16 + i];
    const float inv = 1.f / s;
    const int t = threadIdx.x;
    uint4 hu = *(const uint4*)(g_phi + (size_t)row * SSZ + t * 8);
    uint4 lu = *(const uint4*)(g_plo + (size_t)row * SSZ + t * 8);
    const __nv_bfloat162* hp = (const __nv_bfloat162*)&hu;
    const __nv_bfloat162* lp = (const __nv_bfloat162*)&lu;
    float4 w0, w1;
    w0.x = (__bfloat162float(hp[0].x) + __bfloat162float(lp[0].x)) * inv;
    w0.y = (__bfloat162float(hp[0].y) + __bfloat162float(lp[0].y)) * inv;
    w0.z = (__bfloat162float(hp[1].x) + __bfloat162float(lp[1].x)) * inv;
    w0.w = (__bfloat162float(hp[1].y) + __bfloat162float(lp[1].y)) * inv;
    w1.x = (__bfloat162float(hp[2].x) + __bfloat162float(lp[2].x)) * inv;
    w1.y = (__bfloat162float(hp[2].y) + __bfloat162float(lp[2].y)) * inv;
    w1.z = (__bfloat162float(hp[3].x) + __bfloat162float(lp[3].x)) * inv;
    w1.w = (__bfloat162float(hp[3].y) + __bfloat162float(lp[3].y)) * inv;
    float* wr = W + (size_t)row * SSZ + t * 8;
    *(float4*)(wr)     = w0;
    *(float4*)(wr + 4) = w1;
}

// ---------------- Kernel 5: O = expmap0((P V)/rowsum) -----------------------
// 32(M) x 128(N=D) per CTA => 256 CTAs, 2 CTAs/SM. K=2048 in 64-chunks,
// cp.async double-buffered. 8 warps as 2(M)x4(N), warp tile 16x32.
// smem: inv@0(128B) rp@512(512B) | buffers@2048: {whi,wlo[32][72], vhi,vlo[128][72]} x2
#define APAD 72
#define AV_WT (32 * APAD)
#define AV_VT (128 * APAD)
#define AV_BUF (2 * AV_WT + 2 * AV_VT)
#define AV_SMEM (2048 + 2 * AV_BUF * 2)
__global__ void __launch_bounds__(256, 2)
hyp_av(const float* __restrict__ cp, float* __restrict__ out) {
    extern __shared__ __align__(16) char smem[];
    float* inv_s = (float*)smem;
    float* rp_s = (float*)(smem + 512);
    const uint32_t sb = smem_u32(smem);

    const int tid = threadIdx.x, wid = tid >> 5, lane = tid & 31;
    const int b = blockIdx.z;
    const int row0 = blockIdx.x * 32;

    if (tid < 32) {
        float s = 0.f;
#pragma unroll
        for (int i = 0; i < 16; i++)
            s += g_partial[((size_t)(b * SSZ + row0 + tid)) * 16 + i];
        inv_s[tid] = 1.f / s;
    }

    const __nv_bfloat16* pb_h = g_phi + ((size_t)(b * SSZ + row0)) * SSZ;
    const __nv_bfloat16* pb_l = g_plo + ((size_t)(b * SSZ + row0)) * SSZ;
    const __nv_bfloat16* vth = g_vthi + (size_t)b * DDIM * SSZ;
    const __nv_bfloat16* vtl = g_vtlo + (size_t)b * DDIM * SSZ;

    const uint32_t buf0 = sb + 2048;
    const uint32_t o_wl = AV_WT * 2, o_vh = 2 * AV_WT * 2, o_vl = o_vh + AV_VT * 2;

    auto load_chunk = [&](int stage, int t0) {
        uint32_t base = buf0 + stage * (AV_BUF * 2);
        {
            int r = tid >> 3, g = tid & 7;
            uint32_t so = (uint32_t)(r * (APAD * 2) + g * 16);
            size_t go = (size_t)r * SSZ + t0 + g * 8;
            cpa16(base + so, pb_h + go);
            cpa16(base + o_wl + so, pb_l + go);
        }
#pragma unroll
        for (int it = 0; it < 4; it++) {
            int i = tid + 256 * it;
            int d = i >> 3, g = i & 7;
            uint32_t so = (uint32_t)(d * (APAD * 2) + g * 16);
            size_t go = (size_t)d * SSZ + t0 + g * 8;
            cpa16(base + o_vh + so, vth + go);
            cpa16(base + o_vl + so, vtl + go);
        }
    };

    const int wr = wid >> 2, wc = wid & 3;
    const int m0 = wr * 16, n0 = wc * 32;
    const int alr = lane & 15, alc = (lane >> 4) * 8;

    float acc[4][4];
#pragma unroll
    for (int j = 0; j < 4; j++)
#pragma unroll
        for (int r = 0; r < 4; r++) acc[j][r] = 0.f;

    load_chunk(0, 0);
    CP_COMMIT();

    for (int kc = 0; kc < 32; kc++) {
        if (kc < 31) {
            load_chunk((kc + 1) & 1, (kc + 1) * 64);
            CP_COMMIT();
            CP_WAIT(1);
        } else {
            CP_WAIT(0);
        }
        __syncthreads();

        uint32_t base = buf0 + (kc & 1) * (AV_BUF * 2);
#pragma unroll
        for (int ks = 0; ks < 4; ks++) {
            uint32_t ah[4], al[4], bh[2][4], bl[2][4];
            const int kel = ks * 16 + alc;
            {
                uint32_t off = (uint32_t)(((m0 + alr) * APAD + kel) * 2);
                ldm_x4(ah, base + off);
                ldm_x4(al, base + o_wl + off);
            }
#pragma unroll
            for (int h = 0; h < 2; h++) {
                uint32_t off = (uint32_t)(((n0 + h * 16 + alr) * APAD + kel) * 2);
                ldm_x4(bh[h], base + o_vh + off);
                ldm_x4(bl[h], base + o_vl + off);
            }
#pragma unroll
            for (int fn = 0; fn < 4; fn++) {
                int h = fn >> 1, s = fn & 1;
                mma16816(acc[fn], ah, bh[h][s], bh[h][s + 2]);
                mma16816(acc[fn], ah, bl[h][s], bl[h][s + 2]);
                mma16816(acc[fn], al, bh[h][s], bh[h][s + 2]);
            }
        }
        __syncthreads();
    }

    // epilogue: normalize by rowsum, then exp-map at origin
    const int r1 = m0 + (lane >> 2), r2 = r1 + 8;
    const float i1 = inv_s[r1], i2 = inv_s[r2];
    float s1 = 0.f, s2 = 0.f;
#pragma unroll
    for (int fn = 0; fn < 4; fn++) {
        acc[fn][0] *= i1; acc[fn][1] *= i1;
        acc[fn][2] *= i2; acc[fn][3] *= i2;
        s1 += acc[fn][0] * acc[fn][0] + acc[fn][1] * acc[fn][1];
        s2 += acc[fn][2] * acc[fn][2] + acc[fn][3] * acc[fn][3];
    }
    s1 += __shfl_xor_sync(0xffffffffu, s1, 1);
    s1 += __shfl_xor_sync(0xffffffffu, s1, 2);
    s2 += __shfl_xor_sync(0xffffffffu, s2, 1);
    s2 += __shfl_xor_sync(0xffffffffu, s2, 2);
    if ((lane & 3) == 0) {
        rp_s[r1 * 4 + wc] = s1;
        rp_s[r2 * 4 + wc] = s2;
    }
    __syncthreads();
    const float c = *cp, sqrtc = sqrtf(c);
    float* sc_s = inv_s;   // reuse after inv consumed
    if (tid < 32) {
        float ns = rp_s[tid * 4] + rp_s[tid * 4 + 1] + rp_s[tid * 4 + 2] + rp_s[tid * 4 + 3];
        float vn = fmaxf(sqrtf(ns), EPSV);
        sc_s[tid] = tanhf(sqrtc * vn) / (sqrtc * vn);
    }
    __syncthreads();

    float* ob = out + ((size_t)(b * SSZ + row0)) * DDIM;
    const float sc1 = sc_s[r1], sc2 = sc_s[r2];
#pragma unroll
    for (int fn = 0; fn < 4; fn++) {
        const int cc = n0 + fn * 8 + (lane & 3) * 2;
        *(float2*)(ob + (size_t)r1 * DDIM + cc) =
            make_float2(acc[fn][0] * sc1, acc[fn][1] * sc1);
        *(float2*)(ob + (size_t)r2 * DDIM + cc) =
            make_float2(acc[fn][2] * sc2, acc[fn][3] * sc2);
    }
}

// ---------------------------------------------------------------------------
extern "C" void kernel_launch(void* const* d_in, const int* in_sizes, int n_in,
                              void* d_out, int out_size) {
    const float* q    = (const float*)d_in[0];
    const float* k    = (const float*)d_in[1];
    const float* v    = (const float*)d_in[2];
    const float* c    = (const float*)d_in[3];
    const float* beta = (const float*)d_in[4];

    float* out = (float*)d_out;                   // output_hyperbolic (B,S,D)
    float* W   = out + (size_t)BB * SSZ * DDIM;   // attention_weights (B,S,S)

    cudaFuncSetAttribute(hyp_qk, cudaFuncAttributeMaxDynamicSharedMemorySize, QK_SMEM);
    cudaFuncSetAttribute(hyp_av, cudaFuncAttributeMaxDynamicSharedMemorySize, AV_SMEM);

    hyp_norms<<<2 * BB * SSZ / 8, 256>>>(q, k);
    hyp_vt<<<dim3(SSZ / 32, DDIM / 32, BB), dim3(32, 8)>>>(v);
    hyp_qk<<<dim3(SSZ / 128, SSZ / 128, BB), 256, QK_SMEM>>>(c, beta);
    hyp_norm_w<<<BB * SSZ, 256>>>(W);
    hyp_av<<<dim3(SSZ / 32, 1, BB), 256, AV_SMEM>>>(c, out);
}

// round 10
// speedup vs baseline: 1.7391x; 1.3335x over previous
#include <cuda_runtime.h>
#include <cuda_fp16.h>
#include <cstdint>
#include <math.h>

#define BB 4
#define SSZ 2048
#define DDIM 128
#define EPSV 1e-5f
#define KSCL 256.0f
#define IKSCL (1.0f / 256.0f)

// ---------------- scratch (static device globals; no allocations) ----------
__device__ float g_qnorm[BB * SSZ];
__device__ float g_knorm[BB * SSZ];
__device__ float g_partial[BB * SSZ * 16];
__device__ __half g_qhi[BB * SSZ * DDIM];            // fp16(q)
__device__ __half g_khi[BB * SSZ * DDIM];            // fp16(256*k) hi
__device__ __half g_klo[BB * SSZ * DDIM];            // fp16 residual of 256*k
__device__ __half g_vthi[BB * DDIM * SSZ];           // V^T hi: [b][d][t]
__device__ __half g_vtlo[BB * DDIM * SSZ];           // V^T lo
__device__ __half g_ph[(size_t)BB * SSZ * SSZ];      // unnormalized p (fp16)

// ---------------- helpers ---------------------------------------------------
__device__ __forceinline__ uint32_t smem_u32(const void* p) {
    uint32_t a;
    asm("{ .reg .u64 t; cvta.to.shared.u64 t, %1; cvt.u32.u64 %0, t; }" : "=r"(a) : "l"(p));
    return a;
}
__device__ __forceinline__ void cpa16(uint32_t s, const void* g) {
    asm volatile("cp.async.cg.shared.global [%0], [%1], 16;" :: "r"(s), "l"(g));
}
#define CP_COMMIT() asm volatile("cp.async.commit_group;")
#define CP_WAIT(n)  asm volatile("cp.async.wait_group %0;" :: "n"(n))

__device__ __forceinline__ void ldm_x4(uint32_t r[4], uint32_t addr) {
    asm volatile("ldmatrix.sync.aligned.m8n8.x4.shared.b16 {%0,%1,%2,%3}, [%4];"
        : "=r"(r[0]), "=r"(r[1]), "=r"(r[2]), "=r"(r[3]) : "r"(addr));
}
// D += A*B  (m16n8k16, fp16 in, f32 accum)
__device__ __forceinline__ void mma16816(float c[4], const uint32_t a[4],
                                         uint32_t b0, uint32_t b1) {
    asm volatile("mma.sync.aligned.m16n8k16.row.col.f32.f16.f16.f32 "
        "{%0,%1,%2,%3}, {%4,%5,%6,%7}, {%8,%9}, {%0,%1,%2,%3};"
        : "+f"(c[0]), "+f"(c[1]), "+f"(c[2]), "+f"(c[3])
        : "r"(a[0]), "r"(a[1]), "r"(a[2]), "r"(a[3]), "r"(b0), "r"(b1));
}
__device__ __forceinline__ __half2 h2(float a, float b) {
    return __floats2half2_rn(a, b);
}

// ---------------- Kernel 1: row norms + q fp16 + k(scaled) fp16 hi/lo -------
__global__ __launch_bounds__(256) void hyp_norms(const float* __restrict__ q,
                                                 const float* __restrict__ k) {
    int warp = (blockIdx.x * blockDim.x + threadIdx.x) >> 5;
    int lane = threadIdx.x & 31;
    const int R = BB * SSZ;
    if (warp >= 2 * R) return;
    const bool isq = warp < R;
    const int row = isq ? warp : warp - R;
    const float* src = (isq ? q : k) + (size_t)row * DDIM;
    float4 v = ((const float4*)src)[lane];
    float s = v.x * v.x + v.y * v.y + v.z * v.z + v.w * v.w;
#pragma unroll
    for (int o = 16; o; o >>= 1) s += __shfl_xor_sync(0xffffffffu, s, o);
    if (lane == 0) { if (isq) g_qnorm[row] = s; else g_knorm[row] = s; }

    if (isq) {
        __half* hp = g_qhi + (size_t)row * DDIM + lane * 4;
        *(__half2*)(hp)     = h2(v.x, v.y);
        *(__half2*)(hp + 2) = h2(v.z, v.w);
    } else {
        float4 vs = make_float4(v.x * KSCL, v.y * KSCL, v.z * KSCL, v.w * KSCL);
        __half2 h0 = h2(vs.x, vs.y), h1 = h2(vs.z, vs.w);
        __half2 l0 = h2(vs.x - __half2float(h0.x), vs.y - __half2float(h0.y));
        __half2 l1 = h2(vs.z - __half2float(h1.x), vs.w - __half2float(h1.y));
        __half* hp = g_khi + (size_t)row * DDIM + lane * 4;
        __half* lp = g_klo + (size_t)row * DDIM + lane * 4;
        *(__half2*)(hp)     = h0;
        *(__half2*)(hp + 2) = h1;
        *(__half2*)(lp)     = l0;
        *(__half2*)(lp + 2) = l1;
    }
}

// ---------------- Kernel 2: V^T + fp16 hi/lo split ---------------------------
__global__ void hyp_vt(const float* __restrict__ v) {
    __shared__ float tile[32][33];
    const int b = blockIdx.z, t0 = blockIdx.x * 32, d0 = blockIdx.y * 32;
    const int tx = threadIdx.x, ty = threadIdx.y;
#pragma unroll
    for (int i = 0; i < 4; i++)
        tile[ty + 8 * i][tx] = v[((size_t)(b * SSZ) + t0 + ty + 8 * i) * DDIM + d0 + tx];
    __syncthreads();
#pragma unroll
    for (int i = 0; i < 4; i++) {
        float x = tile[tx][ty + 8 * i];
        __half hi = __float2half_rn(x);
        __half lo = __float2half_rn(x - __half2float(hi));
        size_t idx = ((size_t)(b * DDIM) + d0 + ty + 8 * i) * SSZ + t0 + tx;
        g_vthi[idx] = hi; g_vtlo[idx] = lo;
    }
}

// ---------------- Kernel 3: QK^T (fp16, 2 products) + hyperbolic numerator --
// 128x128 tile/CTA, 8 warps 2x4, warp tile 64x32. Writes p as single fp16.
#define QPAD 136
#define QK_TB (128 * QPAD * 2)
#define QK_SMEM (4096 + 3 * QK_TB)
__global__ void __launch_bounds__(256, 1)
hyp_qk(const float* __restrict__ cp, const float* __restrict__ betap) {
    extern __shared__ __align__(16) char smem[];
    float* qn_s = (float*)smem;
    float* kn_s = (float*)(smem + 512);
    float* iq_s = (float*)(smem + 1024);
    float* ik_s = (float*)(smem + 1536);
    float* rp_s = (float*)(smem + 2048);
    const uint32_t sb = smem_u32(smem);
    const uint32_t t_qh = sb + 4096, t_kh = t_qh + QK_TB, t_kl = t_kh + QK_TB;

    const int tid = threadIdx.x, wid = tid >> 5, lane = tid & 31;
    const int bxx = blockIdx.x, b = blockIdx.z;
    const int row0 = blockIdx.y * 128, col0 = bxx * 128;
    const float c = *cp;

    if (tid < 128) {
        float qn = g_qnorm[b * SSZ + row0 + tid];
        float kn = g_knorm[b * SSZ + col0 + tid];
        qn_s[tid] = qn; kn_s[tid] = kn;
        iq_s[tid] = 1.f / fmaxf(1.f - c * qn, 1e-12f);
        ik_s[tid] = 1.f / fmaxf(1.f - c * kn, 1e-12f);
    }

    {
        const __half* gq_h = g_qhi + (size_t)(b * SSZ + row0) * DDIM;
        const __half* gk_h = g_khi + (size_t)(b * SSZ + col0) * DDIM;
        const __half* gk_l = g_klo + (size_t)(b * SSZ + col0) * DDIM;
#pragma unroll
        for (int it = 0; it < 8; it++) {
            int i = tid + 256 * it;
            int r = i >> 4, g = i & 15;
            uint32_t so = (uint32_t)(r * (QPAD * 2) + g * 16);
            size_t go = (size_t)r * DDIM + g * 8;
            cpa16(t_qh + so, gq_h + go);
            cpa16(t_kh + so, gk_h + go);
            cpa16(t_kl + so, gk_l + go);
        }
    }
    CP_COMMIT();
    CP_WAIT(0);
    __syncthreads();

    const int wr = wid >> 2, wc = wid & 3;
    const int m0 = wr * 64, n0 = wc * 32;
    const int alr = lane & 15, alc = (lane >> 4) * 8;

    float acc[4][4][4];
#pragma unroll
    for (int i = 0; i < 4; i++)
#pragma unroll
        for (int j = 0; j < 4; j++)
#pragma unroll
            for (int r = 0; r < 4; r++) acc[i][j][r] = 0.f;

#pragma unroll
    for (int ks = 0; ks < 8; ks++) {
        uint32_t ah[4][4], bh[2][4], bl[2][4];
        const int kel = ks * 16 + alc;
#pragma unroll
        for (int fm = 0; fm < 4; fm++) {
            uint32_t off = (uint32_t)(((m0 + fm * 16 + alr) * QPAD + kel) * 2);
            ldm_x4(ah[fm], t_qh + off);
        }
#pragma unroll
        for (int h = 0; h < 2; h++) {
            uint32_t off = (uint32_t)(((n0 + h * 16 + alr) * QPAD + kel) * 2);
            ldm_x4(bh[h], t_kh + off);
            ldm_x4(bl[h], t_kl + off);
        }
#pragma unroll
        for (int fm = 0; fm < 4; fm++)
#pragma unroll
            for (int fn = 0; fn < 4; fn++) {
                int h = fn >> 1, s = fn & 1;
                mma16816(acc[fm][fn], ah[fm], bh[h][s], bh[h][s + 2]);
                mma16816(acc[fm][fn], ah[fm], bl[h][s], bl[h][s + 2]);
            }
    }

    // epilogue: dot = acc/256; p = u^(-bp/sqrt(c)); bias cancels in softmax
    const float sqrtc = sqrtf(c);
    const float beta = *betap;
    const float bp = fmaxf(beta, 0.f) + log1pf(expf(-fabsf(beta)));  // softplus
    const float e2 = bp / sqrtc;
    const float tcc = 2.f * c;

    __half* ph = g_ph + ((size_t)(b * SSZ + row0)) * SSZ + col0;
#pragma unroll
    for (int fm = 0; fm < 4; fm++) {
        const int r1 = m0 + fm * 16 + (lane >> 2), r2 = r1 + 8;
        const float qn1 = qn_s[r1], qn2 = qn_s[r2];
        const float iq1 = iq_s[r1], iq2 = iq_s[r2];
        float s1 = 0.f, s2 = 0.f;
#pragma unroll
        for (int fn = 0; fn < 4; fn++) {
            const int cc = n0 + fn * 8 + (lane & 3) * 2;
            const float kn0 = kn_s[cc], kn1 = kn_s[cc + 1];
            const float ik0 = ik_s[cc], ik1 = ik_s[cc + 1];
            float pv[4];
#pragma unroll
            for (int rr = 0; rr < 2; rr++) {
                float qn = rr ? qn2 : qn1, iq = rr ? iq2 : iq1;
#pragma unroll
                for (int jj = 0; jj < 2; jj++) {
                    float dot = acc[fm][fn][rr * 2 + jj] * IKSCL;
                    float kn = jj ? kn1 : kn0, ik = jj ? ik1 : ik0;
                    float x = tcc * (qn + kn - 2.f * dot) * iq * ik;
                    x = fmaxf(x, EPSV);
                    float t = x * (x + 2.f);
                    float u = (1.f + x) + t * rsqrtf(t);
                    float p = exp2f(-e2 * __log2f(u));
                    pv[rr * 2 + jj] = p;
                    if (rr) s2 += p; else s1 += p;
                }
            }
            *(__half2*)(ph + (size_t)r1 * SSZ + cc) = h2(pv[0], pv[1]);
            *(__half2*)(ph + (size_t)r2 * SSZ + cc) = h2(pv[2], pv[3]);
        }
        s1 += __shfl_xor_sync(0xffffffffu, s1, 1);
        s1 += __shfl_xor_sync(0xffffffffu, s1, 2);
        s2 += __shfl_xor_sync(0xffffffffu, s2, 1);
        s2 += __shfl_xor_sync(0xffffffffu, s2, 2);
        if ((lane & 3) == 0) {
            rp_s[r1 * 4 + wc] = s1;
            rp_s[r2 * 4 + wc] = s2;
        }
    }
    __syncthreads();
    if (tid < 128) {
        float s = rp_s[tid * 4] + rp_s[tid * 4 + 1] + rp_s[tid * 4 + 2] + rp_s[tid * 4 + 3];
        g_partial[((size_t)(b * SSZ + row0 + tid)) * 16 + bxx] = s;
    }
}

// ---------------- Kernel 4: W = p / rowsum  (fp16 -> fp32 streaming) --------
__global__ __launch_bounds__(256) void hyp_norm_w(float* __restrict__ W) {
    const int row = blockIdx.x;
    float s = 0.f;
#pragma unroll
    for (int i = 0; i < 16; i++) s += g_partial[(size_t)row * 16 + i];
    const float inv = 1.f / s;
    const int t = threadIdx.x;
    uint4 hu = *(const uint4*)(g_ph + (size_t)row * SSZ + t * 8);
    const __half2* hp = (const __half2*)&hu;
    float* wr = W + (size_t)row * SSZ + t * 8;
    float4 w0, w1;
    w0.x = __half2float(hp[0].x) * inv;
    w0.y = __half2float(hp[0].y) * inv;
    w0.z = __half2float(hp[1].x) * inv;
    w0.w = __half2float(hp[1].y) * inv;
    w1.x = __half2float(hp[2].x) * inv;
    w1.y = __half2float(hp[2].y) * inv;
    w1.z = __half2float(hp[3].x) * inv;
    w1.w = __half2float(hp[3].y) * inv;
    *(float4*)(wr)     = w0;
    *(float4*)(wr + 4) = w1;
}

// ---------------- Kernel 5: O = expmap0((P V)/rowsum)  (fp16, 2 products) ---
// 32(M) x 128(N=D) per CTA => 256 CTAs. K=2048 in 64-chunks, cp.async 2-stage.
#define APAD 72
#define AV_WT (32 * APAD)
#define AV_VT (128 * APAD)
#define AV_BUF (AV_WT + 2 * AV_VT)
#define AV_SMEM (2048 + 2 * AV_BUF * 2)
__global__ void __launch_bounds__(256, 2)
hyp_av(const float* __restrict__ cp, float* __restrict__ out) {
    extern __shared__ __align__(16) char smem[];
    float* inv_s = (float*)smem;
    float* rp_s = (float*)(smem + 512);
    const uint32_t sb = smem_u32(smem);

    const int tid = threadIdx.x, wid = tid >> 5, lane = tid & 31;
    const int b = blockIdx.z;
    const int row0 = blockIdx.x * 32;

    if (tid < 32) {
        float s = 0.f;
#pragma unroll
        for (int i = 0; i < 16; i++)
            s += g_partial[((size_t)(b * SSZ + row0 + tid)) * 16 + i];
        inv_s[tid] = 1.f / s;
    }

    const __half* pb = g_ph + ((size_t)(b * SSZ + row0)) * SSZ;
    const __half* vth = g_vthi + (size_t)b * DDIM * SSZ;
    const __half* vtl = g_vtlo + (size_t)b * DDIM * SSZ;

    const uint32_t buf0 = sb + 2048;
    const uint32_t o_vh = AV_WT * 2, o_vl = o_vh + AV_VT * 2;

    auto load_chunk = [&](int stage, int t0) {
        uint32_t base = buf0 + stage * (AV_BUF * 2);
        {
            int r = tid >> 3, g = tid & 7;
            uint32_t so = (uint32_t)(r * (APAD * 2) + g * 16);
            cpa16(base + so, pb + (size_t)r * SSZ + t0 + g * 8);
        }
#pragma unroll
        for (int it = 0; it < 4; it++) {
            int i = tid + 256 * it;
            int d = i >> 3, g = i & 7;
            uint32_t so = (uint32_t)(d * (APAD * 2) + g * 16);
            size_t go = (size_t)d * SSZ + t0 + g * 8;
            cpa16(base + o_vh + so, vth + go);
            cpa16(base + o_vl + so, vtl + go);
        }
    };

    const int wr = wid >> 2, wc = wid & 3;
    const int m0 = wr * 16, n0 = wc * 32;
    const int alr = lane & 15, alc = (lane >> 4) * 8;

    float acc[4][4];
#pragma unroll
    for (int j = 0; j < 4; j++)
#pragma unroll
        for (int r = 0; r < 4; r++) acc[j][r] = 0.f;

    load_chunk(0, 0);
    CP_COMMIT();

    for (int kc = 0; kc < 32; kc++) {
        if (kc < 31) {
            load_chunk((kc + 1) & 1, (kc + 1) * 64);
            CP_COMMIT();
            CP_WAIT(1);
        } else {
            CP_WAIT(0);
        }
        __syncthreads();

        uint32_t base = buf0 + (kc & 1) * (AV_BUF * 2);
#pragma unroll
        for (int ks = 0; ks < 4; ks++) {
            uint32_t ah[4], bh[2][4], bl[2][4];
            const int kel = ks * 16 + alc;
            {
                uint32_t off = (uint32_t)(((m0 + alr) * APAD + kel) * 2);
                ldm_x4(ah, base + off);
            }
#pragma unroll
            for (int h = 0; h < 2; h++) {
                uint32_t off = (uint32_t)(((n0 + h * 16 + alr) * APAD + kel) * 2);
                ldm_x4(bh[h], base + o_vh + off);
                ldm_x4(bl[h], base + o_vl + off);
            }
#pragma unroll
            for (int fn = 0; fn < 4; fn++) {
                int h = fn >> 1, s = fn & 1;
                mma16816(acc[fn], ah, bh[h][s], bh[h][s + 2]);
                mma16816(acc[fn], ah, bl[h][s], bl[h][s + 2]);
            }
        }
        __syncthreads();
    }

    // epilogue: normalize by rowsum, then exp-map at origin
    const int r1 = m0 + (lane >> 2), r2 = r1 + 8;
    const float i1 = inv_s[r1], i2 = inv_s[r2];
    float s1 = 0.f, s2 = 0.f;
#pragma unroll
    for (int fn = 0; fn < 4; fn++) {
        acc[fn][0] *= i1; acc[fn][1] *= i1;
        acc[fn][2] *= i2; acc[fn][3] *= i2;
        s1 += acc[fn][0] * acc[fn][0] + acc[fn][1] * acc[fn][1];
        s2 += acc[fn][2] * acc[fn][2] + acc[fn][3] * acc[fn][3];
    }
    s1 += __shfl_xor_sync(0xffffffffu, s1, 1);
    s1 += __shfl_xor_sync(0xffffffffu, s1, 2);
    s2 += __shfl_xor_sync(0xffffffffu, s2, 1);
    s2 += __shfl_xor_sync(0xffffffffu, s2, 2);
    if ((lane & 3) == 0) {
        rp_s[r1 * 4 + wc] = s1;
        rp_s[r2 * 4 + wc] = s2;
    }
    __syncthreads();
    const float c = *cp, sqrtc = sqrtf(c);
    float* sc_s = inv_s;   // reuse after inv consumed
    if (tid < 32) {
        float ns = rp_s[tid * 4] + rp_s[tid * 4 + 1] + rp_s[tid * 4 + 2] + rp_s[tid * 4 + 3];
        float vn = fmaxf(sqrtf(ns), EPSV);
        sc_s[tid] = tanhf(sqrtc * vn) / (sqrtc * vn);
    }
    __syncthreads();

    float* ob = out + ((size_t)(b * SSZ + row0)) * DDIM;
    const float sc1 = sc_s[r1], sc2 = sc_s[r2];
#pragma unroll
    for (int fn = 0; fn < 4; fn++) {
        const int cc = n0 + fn * 8 + (lane & 3) * 2;
        *(float2*)(ob + (size_t)r1 * DDIM + cc) =
            make_float2(acc[fn][0] * sc1, acc[fn][1] * sc1);
        *(float2*)(ob + (size_t)r2 * DDIM + cc) =
            make_float2(acc[fn][2] * sc2, acc[fn][3] * sc2);
    }
}

// ---------------------------------------------------------------------------
extern "C" void kernel_launch(void* const* d_in, const int* in_sizes, int n_in,
                              void* d_out, int out_size) {
    const float* q    = (const float*)d_in[0];
    const float* k    = (const float*)d_in[1];
    const float* v    = (const float*)d_in[2];
    const float* c    = (const float*)d_in[3];
    const float* beta = (const float*)d_in[4];

    float* out = (float*)d_out;                   // output_hyperbolic (B,S,D)
    float* W   = out + (size_t)BB * SSZ * DDIM;   // attention_weights (B,S,S)

    cudaFuncSetAttribute(hyp_qk, cudaFuncAttributeMaxDynamicSharedMemorySize, QK_SMEM);
    cudaFuncSetAttribute(hyp_av, cudaFuncAttributeMaxDynamicSharedMemorySize, AV_SMEM);

    hyp_norms<<<2 * BB * SSZ / 8, 256>>>(q, k);
    hyp_vt<<<dim3(SSZ / 32, DDIM / 32, BB), dim3(32, 8)>>>(v);
    hyp_qk<<<dim3(SSZ / 128, SSZ / 128, BB), 256, QK_SMEM>>>(c, beta);
    hyp_norm_w<<<BB * SSZ, 256>>>(W);
    hyp_av<<<dim3(SSZ / 32, 1, BB), 256, AV_SMEM>>>(c, out);
}

// round 11
// speedup vs baseline: 1.8891x; 1.0863x over previous
#include <cuda_runtime.h>
#include <cuda_fp16.h>
#include <cstdint>
#include <math.h>

#define BB 4
#define SSZ 2048
#define DDIM 128
#define EPSV 1e-5f
#define KSCL 256.0f
#define IKSCL (1.0f / 256.0f)

// ---------------- scratch (static device globals; no allocations) ----------
__device__ float g_qnorm[BB * SSZ];
__device__ float g_knorm[BB * SSZ];
__device__ float g_partial[BB * SSZ * 16];
__device__ __half g_qhi[BB * SSZ * DDIM];            // fp16(q)
__device__ __half g_khi[BB * SSZ * DDIM];            // fp16(256*k) hi
__device__ __half g_klo[BB * SSZ * DDIM];            // fp16 residual of 256*k
__device__ __half g_vthi[BB * DDIM * SSZ];           // V^T hi: [b][d][t]
__device__ __half g_vtlo[BB * DDIM * SSZ];           // V^T lo
__device__ __half g_ph[(size_t)BB * SSZ * SSZ];      // unnormalized p (fp16)

// ---------------- helpers ---------------------------------------------------
__device__ __forceinline__ uint32_t smem_u32(const void* p) {
    uint32_t a;
    asm("{ .reg .u64 t; cvta.to.shared.u64 t, %1; cvt.u32.u64 %0, t; }" : "=r"(a) : "l"(p));
    return a;
}
__device__ __forceinline__ void cpa16(uint32_t s, const void* g) {
    asm volatile("cp.async.cg.shared.global [%0], [%1], 16;" :: "r"(s), "l"(g));
}
#define CP_COMMIT() asm volatile("cp.async.commit_group;")
#define CP_WAIT(n)  asm volatile("cp.async.wait_group %0;" :: "n"(n))

__device__ __forceinline__ void ldm_x4(uint32_t r[4], uint32_t addr) {
    asm volatile("ldmatrix.sync.aligned.m8n8.x4.shared.b16 {%0,%1,%2,%3}, [%4];"
        : "=r"(r[0]), "=r"(r[1]), "=r"(r[2]), "=r"(r[3]) : "r"(addr));
}
// D += A*B  (m16n8k16, fp16 in, f32 accum)
__device__ __forceinline__ void mma16816(float c[4], const uint32_t a[4],
                                         uint32_t b0, uint32_t b1) {
    asm volatile("mma.sync.aligned.m16n8k16.row.col.f32.f16.f16.f32 "
        "{%0,%1,%2,%3}, {%4,%5,%6,%7}, {%8,%9}, {%0,%1,%2,%3};"
        : "+f"(c[0]), "+f"(c[1]), "+f"(c[2]), "+f"(c[3])
        : "r"(a[0]), "r"(a[1]), "r"(a[2]), "r"(a[3]), "r"(b0), "r"(b1));
}
__device__ __forceinline__ __half2 h2(float a, float b) {
    return __floats2half2_rn(a, b);
}

// ---------------- Kernel 1: row norms + q fp16 + k(scaled) fp16 hi/lo -------
__global__ __launch_bounds__(256) void hyp_norms(const float* __restrict__ q,
                                                 const float* __restrict__ k) {
    int warp = (blockIdx.x * blockDim.x + threadIdx.x) >> 5;
    int lane = threadIdx.x & 31;
    const int R = BB * SSZ;
    if (warp >= 2 * R) return;
    const bool isq = warp < R;
    const int row = isq ? warp : warp - R;
    const float* src = (isq ? q : k) + (size_t)row * DDIM;
    float4 v = ((const float4*)src)[lane];
    float s = v.x * v.x + v.y * v.y + v.z * v.z + v.w * v.w;
#pragma unroll
    for (int o = 16; o; o >>= 1) s += __shfl_xor_sync(0xffffffffu, s, o);
    if (lane == 0) { if (isq) g_qnorm[row] = s; else g_knorm[row] = s; }

    if (isq) {
        __half* hp = g_qhi + (size_t)row * DDIM + lane * 4;
        *(__half2*)(hp)     = h2(v.x, v.y);
        *(__half2*)(hp + 2) = h2(v.z, v.w);
    } else {
        float4 vs = make_float4(v.x * KSCL, v.y * KSCL, v.z * KSCL, v.w * KSCL);
        __half2 h0 = h2(vs.x, vs.y), h1 = h2(vs.z, vs.w);
        __half2 l0 = h2(vs.x - __half2float(h0.x), vs.y - __half2float(h0.y));
        __half2 l1 = h2(vs.z - __half2float(h1.x), vs.w - __half2float(h1.y));
        __half* hp = g_khi + (size_t)row * DDIM + lane * 4;
        __half* lp = g_klo + (size_t)row * DDIM + lane * 4;
        *(__half2*)(hp)     = h0;
        *(__half2*)(hp + 2) = h1;
        *(__half2*)(lp)     = l0;
        *(__half2*)(lp + 2) = l1;
    }
}

// ---------------- Kernel 2: V^T + fp16 hi/lo split ---------------------------
__global__ void hyp_vt(const float* __restrict__ v) {
    __shared__ float tile[32][33];
    const int b = blockIdx.z, t0 = blockIdx.x * 32, d0 = blockIdx.y * 32;
    const int tx = threadIdx.x, ty = threadIdx.y;
#pragma unroll
    for (int i = 0; i < 4; i++)
        tile[ty + 8 * i][tx] = v[((size_t)(b * SSZ) + t0 + ty + 8 * i) * DDIM + d0 + tx];
    __syncthreads();
#pragma unroll
    for (int i = 0; i < 4; i++) {
        float x = tile[tx][ty + 8 * i];
        __half hi = __float2half_rn(x);
        __half lo = __float2half_rn(x - __half2float(hi));
        size_t idx = ((size_t)(b * DDIM) + d0 + ty + 8 * i) * SSZ + t0 + tx;
        g_vthi[idx] = hi; g_vtlo[idx] = lo;
    }
}

// ---------------- Kernel 3: QK^T (fp16, 2 products) + hyperbolic numerator --
// 128x128 tile/CTA, 8 warps 2x4, warp tile 64x32. Writes p as single fp16.
#define QPAD 136
#define QK_TB (128 * QPAD * 2)
#define QK_SMEM (4096 + 3 * QK_TB)
__global__ void __launch_bounds__(256, 1)
hyp_qk(const float* __restrict__ cp, const float* __restrict__ betap) {
    extern __shared__ __align__(16) char smem[];
    float* qn_s = (float*)smem;
    float* kn_s = (float*)(smem + 512);
    float* iq_s = (float*)(smem + 1024);
    float* ik_s = (float*)(smem + 1536);
    float* rp_s = (float*)(smem + 2048);
    const uint32_t sb = smem_u32(smem);
    const uint32_t t_qh = sb + 4096, t_kh = t_qh + QK_TB, t_kl = t_kh + QK_TB;

    const int tid = threadIdx.x, wid = tid >> 5, lane = tid & 31;
    const int bxx = blockIdx.x, b = blockIdx.z;
    const int row0 = blockIdx.y * 128, col0 = bxx * 128;
    const float c = *cp;

    if (tid < 128) {
        float qn = g_qnorm[b * SSZ + row0 + tid];
        float kn = g_knorm[b * SSZ + col0 + tid];
        qn_s[tid] = qn; kn_s[tid] = kn;
        iq_s[tid] = 1.f / fmaxf(1.f - c * qn, 1e-12f);
        ik_s[tid] = 1.f / fmaxf(1.f - c * kn, 1e-12f);
    }

    {
        const __half* gq_h = g_qhi + (size_t)(b * SSZ + row0) * DDIM;
        const __half* gk_h = g_khi + (size_t)(b * SSZ + col0) * DDIM;
        const __half* gk_l = g_klo + (size_t)(b * SSZ + col0) * DDIM;
#pragma unroll
        for (int it = 0; it < 8; it++) {
            int i = tid + 256 * it;
            int r = i >> 4, g = i & 15;
            uint32_t so = (uint32_t)(r * (QPAD * 2) + g * 16);
            size_t go = (size_t)r * DDIM + g * 8;
            cpa16(t_qh + so, gq_h + go);
            cpa16(t_kh + so, gk_h + go);
            cpa16(t_kl + so, gk_l + go);
        }
    }
    CP_COMMIT();
    CP_WAIT(0);
    __syncthreads();

    const int wr = wid >> 2, wc = wid & 3;
    const int m0 = wr * 64, n0 = wc * 32;
    const int alr = lane & 15, alc = (lane >> 4) * 8;

    float acc[4][4][4];
#pragma unroll
    for (int i = 0; i < 4; i++)
#pragma unroll
        for (int j = 0; j < 4; j++)
#pragma unroll
            for (int r = 0; r < 4; r++) acc[i][j][r] = 0.f;

#pragma unroll
    for (int ks = 0; ks < 8; ks++) {
        uint32_t ah[4][4], bh[2][4], bl[2][4];
        const int kel = ks * 16 + alc;
#pragma unroll
        for (int fm = 0; fm < 4; fm++) {
            uint32_t off = (uint32_t)(((m0 + fm * 16 + alr) * QPAD + kel) * 2);
            ldm_x4(ah[fm], t_qh + off);
        }
#pragma unroll
        for (int h = 0; h < 2; h++) {
            uint32_t off = (uint32_t)(((n0 + h * 16 + alr) * QPAD + kel) * 2);
            ldm_x4(bh[h], t_kh + off);
            ldm_x4(bl[h], t_kl + off);
        }
#pragma unroll
        for (int fm = 0; fm < 4; fm++)
#pragma unroll
            for (int fn = 0; fn < 4; fn++) {
                int h = fn >> 1, s = fn & 1;
                mma16816(acc[fm][fn], ah[fm], bh[h][s], bh[h][s + 2]);
                mma16816(acc[fm][fn], ah[fm], bl[h][s], bl[h][s + 2]);
            }
    }

    // epilogue: dot = acc/256; p = u^(-bp/sqrt(c)); bias cancels in softmax
    const float sqrtc = sqrtf(c);
    const float beta = *betap;
    const float bp = fmaxf(beta, 0.f) + log1pf(expf(-fabsf(beta)));  // softplus
    const float e2 = bp / sqrtc;
    const float tcc = 2.f * c;

    __half* ph = g_ph + ((size_t)(b * SSZ + row0)) * SSZ + col0;
#pragma unroll
    for (int fm = 0; fm < 4; fm++) {
        const int r1 = m0 + fm * 16 + (lane >> 2), r2 = r1 + 8;
        const float qn1 = qn_s[r1], qn2 = qn_s[r2];
        const float iq1 = iq_s[r1], iq2 = iq_s[r2];
        float s1 = 0.f, s2 = 0.f;
#pragma unroll
        for (int fn = 0; fn < 4; fn++) {
            const int cc = n0 + fn * 8 + (lane & 3) * 2;
            const float kn0 = kn_s[cc], kn1 = kn_s[cc + 1];
            const float ik0 = ik_s[cc], ik1 = ik_s[cc + 1];
            float pv[4];
#pragma unroll
            for (int rr = 0; rr < 2; rr++) {
                float qn = rr ? qn2 : qn1, iq = rr ? iq2 : iq1;
#pragma unroll
                for (int jj = 0; jj < 2; jj++) {
                    float dot = acc[fm][fn][rr * 2 + jj] * IKSCL;
                    float kn = jj ? kn1 : kn0, ik = jj ? ik1 : ik0;
                    float x = tcc * (qn + kn - 2.f * dot) * iq * ik;
                    x = fmaxf(x, EPSV);
                    float t = x * (x + 2.f);
                    float u = (1.f + x) + t * rsqrtf(t);
                    float p = exp2f(-e2 * __log2f(u));
                    pv[rr * 2 + jj] = p;
                    if (rr) s2 += p; else s1 += p;
                }
            }
            *(__half2*)(ph + (size_t)r1 * SSZ + cc) = h2(pv[0], pv[1]);
            *(__half2*)(ph + (size_t)r2 * SSZ + cc) = h2(pv[2], pv[3]);
        }
        s1 += __shfl_xor_sync(0xffffffffu, s1, 1);
        s1 += __shfl_xor_sync(0xffffffffu, s1, 2);
        s2 += __shfl_xor_sync(0xffffffffu, s2, 1);
        s2 += __shfl_xor_sync(0xffffffffu, s2, 2);
        if ((lane & 3) == 0) {
            rp_s[r1 * 4 + wc] = s1;
            rp_s[r2 * 4 + wc] = s2;
        }
    }
    __syncthreads();
    if (tid < 128) {
        float s = rp_s[tid * 4] + rp_s[tid * 4 + 1] + rp_s[tid * 4 + 2] + rp_s[tid * 4 + 3];
        g_partial[((size_t)(b * SSZ + row0 + tid)) * 16 + bxx] = s;
    }
}

// ---------------- Kernel 4: O = expmap0((P V)/rowsum) + W = P/rowsum --------
// 32(M) x 128(N=D) per CTA => 256 CTAs, 2 CTAs/SM. K=2048 in 64-chunks,
// cp.async double-buffered. Emits the normalized fp32 W tile from each
// resident p chunk (p read from smem once; 1 uint4 load + 2 float4 stores/thr).
#define APAD 72
#define AV_WT (32 * APAD)
#define AV_VT (128 * APAD)
#define AV_BUF (AV_WT + 2 * AV_VT)
#define AV_SMEM (2048 + 2 * AV_BUF * 2)
__global__ void __launch_bounds__(256, 2)
hyp_av(const float* __restrict__ cp, float* __restrict__ W,
       float* __restrict__ out) {
    extern __shared__ __align__(16) char smem[];
    float* inv_s = (float*)smem;
    float* rp_s = (float*)(smem + 512);
    const uint32_t sb = smem_u32(smem);

    const int tid = threadIdx.x, wid = tid >> 5, lane = tid & 31;
    const int b = blockIdx.z;
    const int row0 = blockIdx.x * 32;

    if (tid < 32) {
        float s = 0.f;
#pragma unroll
        for (int i = 0; i < 16; i++)
            s += g_partial[((size_t)(b * SSZ + row0 + tid)) * 16 + i];
        inv_s[tid] = 1.f / s;
    }

    const __half* pb = g_ph + ((size_t)(b * SSZ + row0)) * SSZ;
    const __half* vth = g_vthi + (size_t)b * DDIM * SSZ;
    const __half* vtl = g_vtlo + (size_t)b * DDIM * SSZ;
    float* wrow = W + ((size_t)(b * SSZ + row0)) * SSZ;

    const uint32_t buf0 = sb + 2048;
    const uint32_t o_vh = AV_WT * 2, o_vl = o_vh + AV_VT * 2;

    auto load_chunk = [&](int stage, int t0) {
        uint32_t base = buf0 + stage * (AV_BUF * 2);
        {
            int r = tid >> 3, g = tid & 7;
            uint32_t so = (uint32_t)(r * (APAD * 2) + g * 16);
            cpa16(base + so, pb + (size_t)r * SSZ + t0 + g * 8);
        }
#pragma unroll
        for (int it = 0; it < 4; it++) {
            int i = tid + 256 * it;
            int d = i >> 3, g = i & 7;
            uint32_t so = (uint32_t)(d * (APAD * 2) + g * 16);
            size_t go = (size_t)d * SSZ + t0 + g * 8;
            cpa16(base + o_vh + so, vth + go);
            cpa16(base + o_vl + so, vtl + go);
        }
    };

    const int wr = wid >> 2, wc = wid & 3;
    const int m0 = wr * 16, n0 = wc * 32;
    const int alr = lane & 15, alc = (lane >> 4) * 8;

    // sync-free per-thread W-emit coords: 32 rows x 64 cols / 256 thr = 8 elems
    const int er = tid >> 3, ecg = (tid & 7) * 8;

    float acc[4][4];
#pragma unroll
    for (int j = 0; j < 4; j++)
#pragma unroll
        for (int r = 0; r < 4; r++) acc[j][r] = 0.f;

    load_chunk(0, 0);
    CP_COMMIT();

    for (int kc = 0; kc < 32; kc++) {
        if (kc < 31) {
            load_chunk((kc + 1) & 1, (kc + 1) * 64);
            CP_COMMIT();
            CP_WAIT(1);
        } else {
            CP_WAIT(0);
        }
        __syncthreads();

        uint32_t base = buf0 + (kc & 1) * (AV_BUF * 2);

        // --- emit normalized fp32 W tile from resident p chunk ---
        {
            const float inv = inv_s[er];
            const char* sp = smem + 2048 + (kc & 1) * (AV_BUF * 2);
            uint4 hu = *(const uint4*)(sp + er * (APAD * 2) + ecg * 2);
            const __half2* hp = (const __half2*)&hu;
            float4 w0, w1;
            w0.x = __half2float(hp[0].x) * inv;
            w0.y = __half2float(hp[0].y) * inv;
            w0.z = __half2float(hp[1].x) * inv;
            w0.w = __half2float(hp[1].y) * inv;
            w1.x = __half2float(hp[2].x) * inv;
            w1.y = __half2float(hp[2].y) * inv;
            w1.z = __half2float(hp[3].x) * inv;
            w1.w = __half2float(hp[3].y) * inv;
            float* wdst = wrow + (size_t)er * SSZ + kc * 64 + ecg;
            *(float4*)(wdst)     = w0;
            *(float4*)(wdst + 4) = w1;
        }

#pragma unroll
        for (int ks = 0; ks < 4; ks++) {
            uint32_t ah[4], bh[2][4], bl[2][4];
            const int kel = ks * 16 + alc;
            {
                uint32_t off = (uint32_t)(((m0 + alr) * APAD + kel) * 2);
                ldm_x4(ah, base + off);
            }
#pragma unroll
            for (int h = 0; h < 2; h++) {
                uint32_t off = (uint32_t)(((n0 + h * 16 + alr) * APAD + kel) * 2);
                ldm_x4(bh[h], base + o_vh + off);
                ldm_x4(bl[h], base + o_vl + off);
            }
#pragma unroll
            for (int fn = 0; fn < 4; fn++) {
                int h = fn >> 1, s = fn & 1;
                mma16816(acc[fn], ah, bh[h][s], bh[h][s + 2]);
                mma16816(acc[fn], ah, bl[h][s], bl[h][s + 2]);
            }
        }
        __syncthreads();
    }

    // epilogue: normalize by rowsum, then exp-map at origin
    const int r1 = m0 + (lane >> 2), r2 = r1 + 8;
    const float i1 = inv_s[r1], i2 = inv_s[r2];
    float s1 = 0.f, s2 = 0.f;
#pragma unroll
    for (int fn = 0; fn < 4; fn++) {
        acc[fn][0] *= i1; acc[fn][1] *= i1;
        acc[fn][2] *= i2; acc[fn][3] *= i2;
        s1 += acc[fn][0] * acc[fn][0] + acc[fn][1] * acc[fn][1];
        s2 += acc[fn][2] * acc[fn][2] + acc[fn][3] * acc[fn][3];
    }
    s1 += __shfl_xor_sync(0xffffffffu, s1, 1);
    s1 += __shfl_xor_sync(0xffffffffu, s1, 2);
    s2 += __shfl_xor_sync(0xffffffffu, s2, 1);
    s2 += __shfl_xor_sync(0xffffffffu, s2, 2);
    if ((lane & 3) == 0) {
        rp_s[r1 * 4 + wc] = s1;
        rp_s[r2 * 4 + wc] = s2;
    }
    __syncthreads();
    const float c = *cp, sqrtc = sqrtf(c);
    float* sc_s = (float*)(smem + 256);   // separate from inv_s region
    if (tid < 32) {
        float ns = rp_s[tid * 4] + rp_s[tid * 4 + 1] + rp_s[tid * 4 + 2] + rp_s[tid * 4 + 3];
        float vn = fmaxf(sqrtf(ns), EPSV);
        sc_s[tid] = tanhf(sqrtc * vn) / (sqrtc * vn);
    }
    __syncthreads();

    float* ob = out + ((size_t)(b * SSZ + row0)) * DDIM;
    const float sc1 = sc_s[r1], sc2 = sc_s[r2];
#pragma unroll
    for (int fn = 0; fn < 4; fn++) {
        const int cc = n0 + fn * 8 + (lane & 3) * 2;
        *(float2*)(ob + (size_t)r1 * DDIM + cc) =
            make_float2(acc[fn][0] * sc1, acc[fn][1] * sc1);
        *(float2*)(ob + (size_t)r2 * DDIM + cc) =
            make_float2(acc[fn][2] * sc2, acc[fn][3] * sc2);
    }
}

// ---------------------------------------------------------------------------
extern "C" void kernel_launch(void* const* d_in, const int* in_sizes, int n_in,
                              void* d_out, int out_size) {
    const float* q    = (const float*)d_in[0];
    const float* k    = (const float*)d_in[1];
    const float* v    = (const float*)d_in[2];
    const float* c    = (const float*)d_in[3];
    const float* beta = (const float*)d_in[4];

    float* out = (float*)d_out;                   // output_hyperbolic (B,S,D)
    float* W   = out + (size_t)BB * SSZ * DDIM;   // attention_weights (B,S,S)

    cudaFuncSetAttribute(hyp_qk, cudaFuncAttributeMaxDynamicSharedMemorySize, QK_SMEM);
    cudaFuncSetAttribute(hyp_av, cudaFuncAttributeMaxDynamicSharedMemorySize, AV_SMEM);

    hyp_norms<<<2 * BB * SSZ / 8, 256>>>(q, k);
    hyp_vt<<<dim3(SSZ / 32, DDIM / 32, BB), dim3(32, 8)>>>(v);
    hyp_qk<<<dim3(SSZ / 128, SSZ / 128, BB), 256, QK_SMEM>>>(c, beta);
    hyp_av<<<dim3(SSZ / 32, 1, BB), 256, AV_SMEM>>>(c, W, out);
}